// round 1
// baseline (speedup 1.0000x reference)
#include <cuda_runtime.h>
#include <math_constants.h>

#define EMBED   512
#define MAXLEN  2048
#define B2      256
#define NTHREADS 1024
#define NWARPS  (NTHREADS / 32)

// Precomputed folded vector v = W^T * weight_vec and scalar c = bias . weight_vec
__device__ float g_v[EMBED];
__device__ float g_c;

// ---------------------------------------------------------------------------
// Kernel 1: fold the Linear into a single vector. 1 block x 512 threads.
// v[d] = sum_e W[e,d] * wv[e];  c = sum_e b[e]*wv[e]
// ---------------------------------------------------------------------------
__global__ void prep_kernel(const float* __restrict__ W,
                            const float* __restrict__ bias,
                            const float* __restrict__ wv) {
    __shared__ float swv[EMBED];
    __shared__ float sred[EMBED];
    int d = threadIdx.x;  // 0..511
    swv[d] = wv[d];
    __syncthreads();

    float s = 0.0f;
    #pragma unroll 8
    for (int e = 0; e < EMBED; ++e) {
        s += W[e * EMBED + d] * swv[e];   // coalesced across d
    }
    g_v[d] = s;

    // block-reduce bias . wv
    sred[d] = bias[d] * swv[d];
    __syncthreads();
    for (int stride = EMBED / 2; stride > 0; stride >>= 1) {
        if (d < stride) sred[d] += sred[d + stride];
        __syncthreads();
    }
    if (d == 0) g_c = sred[0];
}

// ---------------------------------------------------------------------------
// Kernel 2: per-batch-row matvec + masked softmax.
// One CTA per batch row (256 CTAs x 1024 threads -> one full wave).
// Warp-per-token dot product, float4 coalesced loads.
// ---------------------------------------------------------------------------
__global__ __launch_bounds__(NTHREADS, 2)
void attn_kernel(const float* __restrict__ q,
                 const int*   __restrict__ lens,
                 float*       __restrict__ out) {
    __shared__ float sv[EMBED];        // folded vector
    __shared__ float se[MAXLEN];       // energies for this row
    __shared__ float sred[NWARPS];     // cross-warp reduction scratch

    const int tid  = threadIdx.x;
    const int warp = tid >> 5;
    const int lane = tid & 31;
    const int b    = blockIdx.x;

    // load v into shared
    for (int i = tid; i < EMBED; i += NTHREADS) sv[i] = g_v[i];
    __syncthreads();

    const float c = g_c;
    const float4* __restrict__ sv4 = (const float4*)sv;
    const float4* __restrict__ qrow =
        (const float4*)(q + (size_t)b * MAXLEN * EMBED);

    // ---- energies: each warp handles tokens warp, warp+32, ... (64 tokens) ----
    for (int l = warp; l < MAXLEN; l += NWARPS) {
        const float4* __restrict__ qp = qrow + (size_t)l * (EMBED / 4);
        float s = 0.0f;
        #pragma unroll
        for (int k = 0; k < 4; ++k) {
            float4 a  = qp[lane + 32 * k];   // 128B-coalesced per k
            float4 vv = sv4[lane + 32 * k];
            s += a.x * vv.x + a.y * vv.y + a.z * vv.z + a.w * vv.w;
        }
        #pragma unroll
        for (int off = 16; off > 0; off >>= 1)
            s += __shfl_xor_sync(0xffffffffu, s, off);
        if (lane == 0) se[l] = s + c;
    }
    __syncthreads();

    const int len = lens[b];

    // ---- max over valid positions ----
    float m = -CUDART_INF_F;
    for (int l = tid; l < len; l += NTHREADS) m = fmaxf(m, se[l]);
    #pragma unroll
    for (int off = 16; off > 0; off >>= 1)
        m = fmaxf(m, __shfl_xor_sync(0xffffffffu, m, off));
    if (lane == 0) sred[warp] = m;
    __syncthreads();
    if (warp == 0) {
        float mm = sred[lane];   // NWARPS == 32
        #pragma unroll
        for (int off = 16; off > 0; off >>= 1)
            mm = fmaxf(mm, __shfl_xor_sync(0xffffffffu, mm, off));
        if (lane == 0) sred[0] = mm;
    }
    __syncthreads();
    m = sred[0];
    __syncthreads();   // everyone has read sred[0] before it is reused

    // ---- sum of exp over valid positions (write exp back into se) ----
    float ssum = 0.0f;
    for (int l = tid; l < len; l += NTHREADS) {
        float e = __expf(se[l] - m);
        se[l] = e;
        ssum += e;
    }
    #pragma unroll
    for (int off = 16; off > 0; off >>= 1)
        ssum += __shfl_xor_sync(0xffffffffu, ssum, off);
    if (lane == 0) sred[warp] = ssum;
    __syncthreads();
    if (warp == 0) {
        float t = sred[lane];
        #pragma unroll
        for (int off = 16; off > 0; off >>= 1)
            t += __shfl_xor_sync(0xffffffffu, t, off);
        if (lane == 0) sred[0] = t;
    }
    __syncthreads();
    const float inv = 1.0f / sred[0];

    // ---- write output (zeros on masked positions) ----
    float* __restrict__ orow = out + (size_t)b * MAXLEN;
    for (int l = tid; l < MAXLEN; l += NTHREADS)
        orow[l] = (l < len) ? se[l] * inv : 0.0f;
}

// ---------------------------------------------------------------------------
// Launch
// inputs (metadata order): questions, questions_lens, lin_w, lin_b, weight_vec
// ---------------------------------------------------------------------------
extern "C" void kernel_launch(void* const* d_in, const int* in_sizes, int n_in,
                              void* d_out, int out_size) {
    const float* questions = (const float*)d_in[0];
    const int*   lens      = (const int*)  d_in[1];
    const float* lin_w     = (const float*)d_in[2];
    const float* lin_b     = (const float*)d_in[3];
    const float* wv        = (const float*)d_in[4];
    float* out = (float*)d_out;

    prep_kernel<<<1, EMBED>>>(lin_w, lin_b, wv);
    attn_kernel<<<B2, NTHREADS>>>(questions, lens, out);
}

// round 2
// speedup vs baseline: 2.3350x; 2.3350x over previous
#include <cuda_runtime.h>
#include <math_constants.h>

#define EMBED    512
#define MAXLEN   2048
#define B2       256
#define TILE     64            // tokens per energy CTA
#define NTILES   (MAXLEN / TILE)   // 32
#define ETHREADS 256
#define EWARPS   (ETHREADS / 32)   // 8
#define PBLK     16            // partial blocks for prep

// Folded linear: v = W^T * weight_vec, c = bias . weight_vec
__device__ float g_v[EMBED];
__device__ float g_c;
__device__ float g_partial[PBLK][EMBED];
__device__ float g_energy[B2 * MAXLEN];   // 2 MB static scratch

// ---------------------------------------------------------------------------
// Prep 1: partial column sums of W^T * wv. 16 CTAs x 512 threads,
// each CTA handles 32 rows of W (coalesced across d).
// ---------------------------------------------------------------------------
__global__ void prep_partial(const float* __restrict__ W,
                             const float* __restrict__ wv) {
    __shared__ float swv[EMBED / PBLK];   // 32
    const int d   = threadIdx.x;          // 0..511
    const int blk = blockIdx.x;
    const int e0  = blk * (EMBED / PBLK);
    if (d < EMBED / PBLK) swv[d] = wv[e0 + d];
    __syncthreads();

    float s = 0.0f;
    #pragma unroll
    for (int e = 0; e < EMBED / PBLK; ++e)
        s += W[(size_t)(e0 + e) * EMBED + d] * swv[e];
    g_partial[blk][d] = s;
}

// ---------------------------------------------------------------------------
// Prep 2: combine partials + bias dot. 1 CTA x 512 threads.
// ---------------------------------------------------------------------------
__global__ void prep_reduce(const float* __restrict__ bias,
                            const float* __restrict__ wv) {
    __shared__ float sred[EMBED];
    const int d = threadIdx.x;
    float s = 0.0f;
    #pragma unroll
    for (int p = 0; p < PBLK; ++p) s += g_partial[p][d];
    g_v[d] = s;

    sred[d] = bias[d] * wv[d];
    __syncthreads();
    for (int stride = EMBED / 2; stride > 0; stride >>= 1) {
        if (d < stride) sred[d] += sred[d + stride];
        __syncthreads();
    }
    if (d == 0) g_c = sred[0];
}

// ---------------------------------------------------------------------------
// Energies: grid (NTILES, B2). Each CTA handles 64 tokens of one row,
// skipping entirely if the tile is beyond the ragged length.
// Warp-per-token float4 dot products (128B-coalesced).
// ---------------------------------------------------------------------------
__global__ __launch_bounds__(ETHREADS)
void energy_kernel(const float* __restrict__ q,
                   const int*   __restrict__ lens) {
    const int b   = blockIdx.y;
    const int len = lens[b];
    const int l0  = blockIdx.x * TILE;
    if (l0 >= len) return;                // empty tile: no DRAM traffic

    __shared__ float sv[EMBED];
    const int tid  = threadIdx.x;
    const int warp = tid >> 5;
    const int lane = tid & 31;

    for (int i = tid; i < EMBED; i += ETHREADS) sv[i] = g_v[i];
    __syncthreads();

    const float  c   = g_c;
    const float4* __restrict__ sv4  = (const float4*)sv;
    const float4* __restrict__ qrow =
        (const float4*)(q + (size_t)b * MAXLEN * EMBED);
    const int end = min(l0 + TILE, len);

    for (int l = l0 + warp; l < end; l += EWARPS) {
        const float4* __restrict__ qp = qrow + (size_t)l * (EMBED / 4);
        float s = 0.0f;
        #pragma unroll
        for (int k = 0; k < 4; ++k) {
            float4 a  = qp[lane + 32 * k];
            float4 vv = sv4[lane + 32 * k];
            s += a.x * vv.x + a.y * vv.y + a.z * vv.z + a.w * vv.w;
        }
        #pragma unroll
        for (int off = 16; off > 0; off >>= 1)
            s += __shfl_xor_sync(0xffffffffu, s, off);
        if (lane == 0) g_energy[(size_t)b * MAXLEN + l] = s + c;
    }
}

// ---------------------------------------------------------------------------
// Softmax: one CTA per row. Reads len energies, masked softmax, writes 2048.
// ---------------------------------------------------------------------------
#define STHREADS 256
#define SWARPS   (STHREADS / 32)
__global__ __launch_bounds__(STHREADS)
void softmax_kernel(const int* __restrict__ lens,
                    float*     __restrict__ out) {
    __shared__ float se[MAXLEN];
    __shared__ float sred[SWARPS];

    const int b    = blockIdx.x;
    const int len  = lens[b];
    const int tid  = threadIdx.x;
    const int warp = tid >> 5;
    const int lane = tid & 31;
    const float* __restrict__ erow = g_energy + (size_t)b * MAXLEN;

    // load valid energies + max
    float m = -CUDART_INF_F;
    for (int l = tid; l < len; l += STHREADS) {
        float e = erow[l];
        se[l] = e;
        m = fmaxf(m, e);
    }
    #pragma unroll
    for (int off = 16; off > 0; off >>= 1)
        m = fmaxf(m, __shfl_xor_sync(0xffffffffu, m, off));
    if (lane == 0) sred[warp] = m;
    __syncthreads();
    if (warp == 0) {
        float mm = (lane < SWARPS) ? sred[lane] : -CUDART_INF_F;
        #pragma unroll
        for (int off = 16; off > 0; off >>= 1)
            mm = fmaxf(mm, __shfl_xor_sync(0xffffffffu, mm, off));
        if (lane == 0) sred[0] = mm;
    }
    __syncthreads();
    m = sred[0];
    __syncthreads();

    // exp + sum
    float ssum = 0.0f;
    for (int l = tid; l < len; l += STHREADS) {
        float e = __expf(se[l] - m);
        se[l] = e;
        ssum += e;
    }
    #pragma unroll
    for (int off = 16; off > 0; off >>= 1)
        ssum += __shfl_xor_sync(0xffffffffu, ssum, off);
    if (lane == 0) sred[warp] = ssum;
    __syncthreads();
    if (warp == 0) {
        float t = (lane < SWARPS) ? sred[lane] : 0.0f;
        #pragma unroll
        for (int off = 16; off > 0; off >>= 1)
            t += __shfl_xor_sync(0xffffffffu, t, off);
        if (lane == 0) sred[0] = t;
    }
    __syncthreads();
    const float inv = 1.0f / sred[0];

    float* __restrict__ orow = out + (size_t)b * MAXLEN;
    for (int l = tid; l < MAXLEN; l += STHREADS)
        orow[l] = (l < len) ? se[l] * inv : 0.0f;
}

// ---------------------------------------------------------------------------
// Launch. inputs: questions, questions_lens, lin_w, lin_b, weight_vec
// ---------------------------------------------------------------------------
extern "C" void kernel_launch(void* const* d_in, const int* in_sizes, int n_in,
                              void* d_out, int out_size) {
    const float* questions = (const float*)d_in[0];
    const int*   lens      = (const int*)  d_in[1];
    const float* lin_w     = (const float*)d_in[2];
    const float* lin_b     = (const float*)d_in[3];
    const float* wv        = (const float*)d_in[4];
    float* out = (float*)d_out;

    prep_partial<<<PBLK, EMBED>>>(lin_w, wv);
    prep_reduce<<<1, EMBED>>>(lin_b, wv);

    dim3 egrid(NTILES, B2);
    energy_kernel<<<egrid, ETHREADS>>>(questions, lens);
    softmax_kernel<<<B2, STHREADS>>>(lens, out);
}

// round 3
// speedup vs baseline: 2.5621x; 1.0973x over previous
#include <cuda_runtime.h>
#include <math_constants.h>

#define EMBED    512
#define MAXLEN   2048
#define B2       256
#define TILE     128               // tokens per energy CTA
#define NTILES   (MAXLEN / TILE)   // 16
#define ETHREADS 512
#define EWARPS   (ETHREADS / 32)   // 16
#define PBLK     16                // CTAs for prep

// Folded linear: v = W^T * weight_vec, c = bias . weight_vec
__device__ float g_v[EMBED];
__device__ float g_c;
__device__ float g_partial[PBLK][EMBED];
__device__ unsigned int g_cnt;            // zero-init, self-resetting
__device__ float g_energy[B2 * MAXLEN];   // 2 MB static scratch

// ---------------------------------------------------------------------------
// Prep (single launch): 16 CTAs x 512 threads compute partial column sums of
// W^T * wv; the last CTA to finish combines partials and the bias dot.
// ---------------------------------------------------------------------------
__global__ void prep_kernel(const float* __restrict__ W,
                            const float* __restrict__ bias,
                            const float* __restrict__ wv) {
    __shared__ float swv[EMBED / PBLK];   // 32
    __shared__ bool  s_last;
    const int d   = threadIdx.x;          // 0..511
    const int blk = blockIdx.x;
    const int e0  = blk * (EMBED / PBLK);
    if (d < EMBED / PBLK) swv[d] = wv[e0 + d];
    __syncthreads();

    float s = 0.0f;
    #pragma unroll
    for (int e = 0; e < EMBED / PBLK; ++e)
        s += W[(size_t)(e0 + e) * EMBED + d] * swv[e];
    g_partial[blk][d] = s;

    // last-CTA-done combine
    __threadfence();
    if (d == 0) {
        unsigned int prev = atomicAdd(&g_cnt, 1u);
        s_last = (prev == PBLK - 1);
    }
    __syncthreads();
    if (!s_last) return;

    float acc = 0.0f;
    #pragma unroll
    for (int p = 0; p < PBLK; ++p) acc += g_partial[p][d];
    g_v[d] = acc;

    __shared__ float sred[EMBED];
    sred[d] = bias[d] * wv[d];
    __syncthreads();
    for (int stride = EMBED / 2; stride > 0; stride >>= 1) {
        if (d < stride) sred[d] += sred[d + stride];
        __syncthreads();
    }
    if (d == 0) { g_c = sred[0]; g_cnt = 0u; }   // reset for graph replay
}

// ---------------------------------------------------------------------------
// Energies: grid (NTILES, B2). Each CTA: 128 tokens of one row, skipping
// entirely past the ragged length. Warp-per-token, 2 tokens in flight per
// warp (8 outstanding LDG.128 per lane), streaming loads.
// ---------------------------------------------------------------------------
__global__ __launch_bounds__(ETHREADS)
void energy_kernel(const float* __restrict__ q,
                   const int*   __restrict__ lens) {
    const int b   = blockIdx.y;
    const int len = __ldg(lens + b);
    const int l0  = blockIdx.x * TILE;
    if (l0 >= len) return;                // empty tile: zero DRAM traffic

    __shared__ float sv[EMBED];
    const int tid  = threadIdx.x;
    const int warp = tid >> 5;
    const int lane = tid & 31;

    for (int i = tid; i < EMBED; i += ETHREADS) sv[i] = g_v[i];
    __syncthreads();

    const float  c    = g_c;
    const float4* __restrict__ sv4  = (const float4*)sv;
    const float4* __restrict__ qrow =
        (const float4*)(q + (size_t)b * MAXLEN * EMBED);
    const int end = min(l0 + TILE, len);

    float4 vv[4];
    #pragma unroll
    for (int k = 0; k < 4; ++k) vv[k] = sv4[lane + 32 * k];

    float* __restrict__ erow = g_energy + (size_t)b * MAXLEN;

    for (int l = l0 + warp; l < end; l += 2 * EWARPS) {
        const int l2   = l + EWARPS;
        const bool has2 = (l2 < end);
        const float4* __restrict__ qp0 = qrow + (size_t)l  * (EMBED / 4);
        const float4* __restrict__ qp1 = qrow + (size_t)l2 * (EMBED / 4);

        float4 a0[4], a1[4];
        #pragma unroll
        for (int k = 0; k < 4; ++k) a0[k] = __ldcs(qp0 + lane + 32 * k);
        if (has2) {
            #pragma unroll
            for (int k = 0; k < 4; ++k) a1[k] = __ldcs(qp1 + lane + 32 * k);
        }

        float s0 = 0.0f, s1 = 0.0f;
        #pragma unroll
        for (int k = 0; k < 4; ++k)
            s0 += a0[k].x * vv[k].x + a0[k].y * vv[k].y
                + a0[k].z * vv[k].z + a0[k].w * vv[k].w;
        if (has2) {
            #pragma unroll
            for (int k = 0; k < 4; ++k)
                s1 += a1[k].x * vv[k].x + a1[k].y * vv[k].y
                    + a1[k].z * vv[k].z + a1[k].w * vv[k].w;
        }

        #pragma unroll
        for (int off = 16; off > 0; off >>= 1) {
            s0 += __shfl_xor_sync(0xffffffffu, s0, off);
            s1 += __shfl_xor_sync(0xffffffffu, s1, off);
        }
        if (lane == 0) {
            erow[l] = s0 + c;
            if (has2) erow[l2] = s1 + c;
        }
    }
}

// ---------------------------------------------------------------------------
// Softmax: one CTA (512 threads) per row. Masked softmax, float4 stores.
// ---------------------------------------------------------------------------
#define STHREADS 512
#define SWARPS   (STHREADS / 32)   // 16
__global__ __launch_bounds__(STHREADS)
void softmax_kernel(const int* __restrict__ lens,
                    float*     __restrict__ out) {
    __shared__ float se[MAXLEN];
    __shared__ float sred[SWARPS];

    const int b    = blockIdx.x;
    const int len  = __ldg(lens + b);
    const int tid  = threadIdx.x;
    const int warp = tid >> 5;
    const int lane = tid & 31;
    const float* __restrict__ erow = g_energy + (size_t)b * MAXLEN;

    // load valid energies + max
    float m = -CUDART_INF_F;
    for (int l = tid; l < len; l += STHREADS) {
        float e = erow[l];
        se[l] = e;
        m = fmaxf(m, e);
    }
    #pragma unroll
    for (int off = 16; off > 0; off >>= 1)
        m = fmaxf(m, __shfl_xor_sync(0xffffffffu, m, off));
    if (lane == 0) sred[warp] = m;
    __syncthreads();
    if (warp == 0) {
        float mm = (lane < SWARPS) ? sred[lane] : -CUDART_INF_F;
        #pragma unroll
        for (int off = 16; off > 0; off >>= 1)
            mm = fmaxf(mm, __shfl_xor_sync(0xffffffffu, mm, off));
        if (lane == 0) sred[0] = mm;
    }
    __syncthreads();
    m = sred[0];
    __syncthreads();

    // exp + sum
    float ssum = 0.0f;
    for (int l = tid; l < len; l += STHREADS) {
        float e = __expf(se[l] - m);
        se[l] = e;
        ssum += e;
    }
    #pragma unroll
    for (int off = 16; off > 0; off >>= 1)
        ssum += __shfl_xor_sync(0xffffffffu, ssum, off);
    if (lane == 0) sred[warp] = ssum;
    __syncthreads();
    if (warp == 0) {
        float t = (lane < SWARPS) ? sred[lane] : 0.0f;
        #pragma unroll
        for (int off = 16; off > 0; off >>= 1)
            t += __shfl_xor_sync(0xffffffffu, t, off);
        if (lane == 0) sred[0] = t;
    }
    __syncthreads();
    const float inv = 1.0f / sred[0];

    // vectorized masked write: each thread owns one float4 (tid*4 .. tid*4+3)
    float4* __restrict__ orow4 = (float4*)(out + (size_t)b * MAXLEN);
    const int base = tid * 4;    // 512 threads * 4 = 2048
    float4 o;
    o.x = (base + 0 < len) ? se[base + 0] * inv : 0.0f;
    o.y = (base + 1 < len) ? se[base + 1] * inv : 0.0f;
    o.z = (base + 2 < len) ? se[base + 2] * inv : 0.0f;
    o.w = (base + 3 < len) ? se[base + 3] * inv : 0.0f;
    orow4[tid] = o;
}

// ---------------------------------------------------------------------------
// Launch. inputs: questions, questions_lens, lin_w, lin_b, weight_vec
// ---------------------------------------------------------------------------
extern "C" void kernel_launch(void* const* d_in, const int* in_sizes, int n_in,
                              void* d_out, int out_size) {
    const float* questions = (const float*)d_in[0];
    const int*   lens      = (const int*)  d_in[1];
    const float* lin_w     = (const float*)d_in[2];
    const float* lin_b     = (const float*)d_in[3];
    const float* wv        = (const float*)d_in[4];
    float* out = (float*)d_out;

    prep_kernel<<<PBLK, EMBED>>>(lin_w, lin_b, wv);

    dim3 egrid(NTILES, B2);
    energy_kernel<<<egrid, ETHREADS>>>(questions, lens);
    softmax_kernel<<<B2, STHREADS>>>(lens, out);
}